// round 4
// baseline (speedup 1.0000x reference)
#include <cuda_runtime.h>
#include <cuda_bf16.h>
#include <cstdint>
#include <math.h>

// ---------------- problem constants ----------------
#define BT    80
#define MAXN  13
#define M_DIM 1040
#define K_DIM 26400
#define N_DIM 1024
#define A_DIM 6
#define G_DIM 5

// ---------------- GEMM config ----------------
#define K_PAD  26432              // 413 * 64
#define M_PAD  1152
#define KC     64                 // K elements per stage chunk (128B rows)
#define NCHUNK (K_PAD / KC)       // 413
#define GM 64
#define GN 64
#define STAGES 3

#define TILE_BYTES (64 * 128)            // 64 rows x 128B = 8KB
#define STAGE_BYTES (4 * TILE_BYTES)     // Ah, Al, Bh, Bl = 32KB
#define OFF_AH 0
#define OFF_AL (1 * TILE_BYTES)
#define OFF_BH (2 * TILE_BYTES)
#define OFF_BL (3 * TILE_BYTES)
#define SMEM_TOTAL (STAGES * STAGE_BYTES)   // 98304

// ---------------- device scratch ----------------
__device__ __align__(128) __nv_bfloat16 g_Xh[(size_t)M_PAD * K_PAD];
__device__ __align__(128) __nv_bfloat16 g_Xl[(size_t)M_PAD * K_PAD];
__device__ __align__(128) __nv_bfloat16 g_Wh[(size_t)N_DIM * K_PAD];
__device__ __align__(128) __nv_bfloat16 g_Wl[(size_t)N_DIM * K_PAD];
__device__ float g_H[(size_t)M_DIM * N_DIM];
__device__ int   g_rowsrc[M_DIM];   // dense row -> bt*13+n
__device__ int   g_Mvalid;

// ---------------- helpers ----------------
__device__ __forceinline__ uint32_t smem_u32(const void* p) {
    uint32_t a;
    asm("{ .reg .u64 t; cvta.to.shared.u64 t, %1; cvt.u32.u64 %0, t; }" : "=r"(a) : "l"(p));
    return a;
}
__device__ __forceinline__ void cp_async16(uint32_t dst, const void* src) {
    asm volatile("cp.async.cg.shared.global [%0], [%1], 16;" :: "r"(dst), "l"(src));
}
#define CP_COMMIT() asm volatile("cp.async.commit_group;" ::: "memory")
#define CP_WAIT1()  asm volatile("cp.async.wait_group 1;" ::: "memory")

#define LDSM_X4(r0, r1, r2, r3, addr) \
    asm volatile("ldmatrix.sync.aligned.m8n8.x4.shared.b16 {%0,%1,%2,%3}, [%4];" \
        : "=r"(r0), "=r"(r1), "=r"(r2), "=r"(r3) : "r"(addr))

__device__ __forceinline__ void mma_bf16(float* c, const uint32_t* a, const uint32_t* b) {
    asm volatile(
        "mma.sync.aligned.m16n8k16.row.col.f32.bf16.bf16.f32 "
        "{%0,%1,%2,%3}, {%4,%5,%6,%7}, {%8,%9}, {%0,%1,%2,%3};"
        : "+f"(c[0]), "+f"(c[1]), "+f"(c[2]), "+f"(c[3])
        : "r"(a[0]), "r"(a[1]), "r"(a[2]), "r"(a[3]), "r"(b[0]), "r"(b[1]));
}

__device__ __forceinline__ uint32_t swz_addr(uint32_t tile_base, int row, int c) {
    return tile_base + (uint32_t)(row * 128) + (uint32_t)((c ^ (row & 7)) << 4);
}

// Fill 64-row x 128B tile from global bf16 [*, K_PAD]; 256 threads, 2 iters
__device__ __forceinline__ void fill_tile64(uint32_t smem_tile, const __nv_bfloat16* gbase,
                                            int row0, int k0, int tid) {
    const char* base = (const char*)gbase;
    #pragma unroll
    for (int i = 0; i < 2; i++) {
        int idx = tid + i * 256;
        int row = idx >> 3;
        int c   = idx & 7;
        const char* src = base + ((size_t)(row0 + row) * K_PAD + (size_t)k0) * 2 + c * 16;
        cp_async16(swz_addr(smem_tile, row, c), src);
    }
}

// ---------------- Kernel: ragged prefix / row map ----------------
__global__ __launch_bounds__(128)
void prefix_kernel(const int* __restrict__ bboxes_num) {
    __shared__ int pre[BT];
    const int tid = threadIdx.x;
    if (tid == 0) {
        int acc = 0;
        #pragma unroll 1
        for (int i = 0; i < BT; i++) {
            pre[i] = acc;
            int nv = bboxes_num[i];
            nv = nv < 1 ? 1 : (nv > MAXN ? MAXN : nv);
            acc += nv;
        }
        g_Mvalid = acc;
    }
    __syncthreads();
    for (int i = tid; i < BT; i += 128) {
        int base = pre[i];
        int nv = bboxes_num[i];
        nv = nv < 1 ? 1 : (nv > MAXN ? MAXN : nv);
        for (int n = 0; n < nv; n++) g_rowsrc[base + n] = i * MAXN + n;
    }
}

// ---------------- Kernel: fp32 -> bf16 hi/lo split of X (gathered, valid rows only) ----------------
__global__ __launch_bounds__(256)
void convert_x_kernel(const float* __restrict__ X) {
    size_t t = (size_t)blockIdx.x * blockDim.x + threadIdx.x;
    const size_t total = (size_t)M_DIM * (K_DIM / 4);
    if (t >= total) return;
    int d  = (int)(t / (K_DIM / 4));
    if (d >= g_Mvalid) return;
    int kk = (int)(t % (K_DIM / 4)) * 4;
    int src = g_rowsrc[d];
    float4 v = *(const float4*)(X + (size_t)src * K_DIM + kk);
    float f[4] = {v.x, v.y, v.z, v.w};
    uint32_t hi[2], lo[2];
    #pragma unroll
    for (int p = 0; p < 2; p++) {
        __nv_bfloat16 h0 = __float2bfloat16(f[2*p+0]);
        __nv_bfloat16 h1 = __float2bfloat16(f[2*p+1]);
        __nv_bfloat16 l0 = __float2bfloat16(f[2*p+0] - __bfloat162float(h0));
        __nv_bfloat16 l1 = __float2bfloat16(f[2*p+1] - __bfloat162float(h1));
        hi[p] = (uint32_t)__bfloat16_as_ushort(h0) | ((uint32_t)__bfloat16_as_ushort(h1) << 16);
        lo[p] = (uint32_t)__bfloat16_as_ushort(l0) | ((uint32_t)__bfloat16_as_ushort(l1) << 16);
    }
    size_t o = (size_t)d * K_PAD + kk;
    *(uint2*)(g_Xh + o) = make_uint2(hi[0], hi[1]);
    *(uint2*)(g_Xl + o) = make_uint2(lo[0], lo[1]);
}

// ---------------- Kernel: transpose + split W [K,N] -> Wh/Wl [N, K_PAD] ----------------
__global__ __launch_bounds__(256)
void convert_w_kernel(const float* __restrict__ W) {
    __shared__ float s[64][33];
    const int k0 = blockIdx.x * 64;
    const int n0 = blockIdx.y * 32;
    const int tid = threadIdx.x;

    {
        int kr = tid >> 2;
        int nb = (tid & 3) * 8;
        int k = k0 + kr;
        if (k < K_DIM) {
            float4 a = *(const float4*)(W + (size_t)k * N_DIM + n0 + nb);
            float4 b = *(const float4*)(W + (size_t)k * N_DIM + n0 + nb + 4);
            s[kr][nb+0]=a.x; s[kr][nb+1]=a.y; s[kr][nb+2]=a.z; s[kr][nb+3]=a.w;
            s[kr][nb+4]=b.x; s[kr][nb+5]=b.y; s[kr][nb+6]=b.z; s[kr][nb+7]=b.w;
        } else {
            #pragma unroll
            for (int i = 0; i < 8; i++) s[kr][nb+i] = 0.0f;
        }
    }
    __syncthreads();

    {
        int nr = tid >> 3;
        int kb = (tid & 7) * 8;
        uint32_t hi[4], lo[4];
        #pragma unroll
        for (int p = 0; p < 4; p++) {
            float f0 = s[kb + 2*p + 0][nr];
            float f1 = s[kb + 2*p + 1][nr];
            __nv_bfloat16 h0 = __float2bfloat16(f0);
            __nv_bfloat16 h1 = __float2bfloat16(f1);
            __nv_bfloat16 l0 = __float2bfloat16(f0 - __bfloat162float(h0));
            __nv_bfloat16 l1 = __float2bfloat16(f1 - __bfloat162float(h1));
            hi[p] = (uint32_t)__bfloat16_as_ushort(h0) | ((uint32_t)__bfloat16_as_ushort(h1) << 16);
            lo[p] = (uint32_t)__bfloat16_as_ushort(l0) | ((uint32_t)__bfloat16_as_ushort(l1) << 16);
        }
        size_t o = (size_t)(n0 + nr) * K_PAD + k0 + kb;
        *(uint4*)(g_Wh + o) = make_uint4(hi[0], hi[1], hi[2], hi[3]);
        *(uint4*)(g_Wl + o) = make_uint4(lo[0], lo[1], lo[2], lo[3]);
    }
}

// ---------------- Kernel: mma.sync bf16 GEMM (64x64 tile), 3-term split ----------------
__global__ void __launch_bounds__(256, 1)
gemm_kernel(const float* __restrict__ bias) {
    const int bm = blockIdx.y * GM;
    const int mv = g_Mvalid;
    if (bm >= mv) return;                 // ragged early-exit (uniform)

    extern __shared__ char smem[];
    const uint32_t sb = smem_u32(smem);
    const int tid  = threadIdx.x;
    const int lane = tid & 31;
    const int wid  = tid >> 5;
    const int bn = blockIdx.x * GN;
    const int m_off = (wid & 1) * 32;     // 2 warps down M
    const int n_off = (wid >> 1) * 16;    // 4 warps across N

    float acc[2][2][4];
    #pragma unroll
    for (int mi = 0; mi < 2; mi++)
        #pragma unroll
        for (int ni = 0; ni < 2; ni++)
            #pragma unroll
            for (int q = 0; q < 4; q++) acc[mi][ni][q] = 0.0f;

    const int aRow0 = m_off + (lane & 15);
    const int cA    = lane >> 4;
    const int bRowBase = n_off + ((lane & 16) >> 1) + (lane & 7);
    const int cB    = (lane >> 3) & 1;

    #pragma unroll
    for (int j = 0; j < STAGES - 1; j++) {
        uint32_t st = sb + j * STAGE_BYTES;
        fill_tile64(st + OFF_AH, g_Xh, bm, j * KC, tid);
        fill_tile64(st + OFF_AL, g_Xl, bm, j * KC, tid);
        fill_tile64(st + OFF_BH, g_Wh, bn, j * KC, tid);
        fill_tile64(st + OFF_BL, g_Wl, bn, j * KC, tid);
        CP_COMMIT();
    }

    for (int j = 0; j < NCHUNK; j++) {
        CP_WAIT1();
        __syncthreads();

        if (j + 2 < NCHUNK) {
            uint32_t st = sb + ((j + 2) % STAGES) * STAGE_BYTES;
            fill_tile64(st + OFF_AH, g_Xh, bm, (j + 2) * KC, tid);
            fill_tile64(st + OFF_AL, g_Xl, bm, (j + 2) * KC, tid);
            fill_tile64(st + OFF_BH, g_Wh, bn, (j + 2) * KC, tid);
            fill_tile64(st + OFF_BL, g_Wl, bn, (j + 2) * KC, tid);
        }
        CP_COMMIT();

        const uint32_t st = sb + (j % STAGES) * STAGE_BYTES;
        #pragma unroll
        for (int kk = 0; kk < 4; kk++) {
            uint32_t ah[2][4], al[2][4], bh[4], bl[4];
            #pragma unroll
            for (int mi = 0; mi < 2; mi++) {
                LDSM_X4(ah[mi][0], ah[mi][1], ah[mi][2], ah[mi][3],
                        swz_addr(st + OFF_AH, aRow0 + mi * 16, kk * 2 + cA));
                LDSM_X4(al[mi][0], al[mi][1], al[mi][2], al[mi][3],
                        swz_addr(st + OFF_AL, aRow0 + mi * 16, kk * 2 + cA));
            }
            LDSM_X4(bh[0], bh[1], bh[2], bh[3],
                    swz_addr(st + OFF_BH, bRowBase, kk * 2 + cB));
            LDSM_X4(bl[0], bl[1], bl[2], bl[3],
                    swz_addr(st + OFF_BL, bRowBase, kk * 2 + cB));
            #pragma unroll
            for (int mi = 0; mi < 2; mi++) {
                #pragma unroll
                for (int ni = 0; ni < 2; ni++) {
                    mma_bf16(acc[mi][ni], ah[mi], &bh[ni * 2]);   // Ah*Bh
                    mma_bf16(acc[mi][ni], ah[mi], &bl[ni * 2]);   // Ah*Bl
                    mma_bf16(acc[mi][ni], al[mi], &bh[ni * 2]);   // Al*Bh
                }
            }
        }
        __syncthreads();
    }

    // epilogue: bias + ReLU, scatter dense row -> original (bt,n) slot in g_H
    #pragma unroll
    for (int mi = 0; mi < 2; mi++) {
        #pragma unroll
        for (int ni = 0; ni < 2; ni++) {
            int gm0 = bm + m_off + mi * 16 + (lane >> 2);
            int gn  = bn + n_off + ni * 8 + (lane & 3) * 2;
            float b0 = bias[gn], b1 = bias[gn + 1];
            if (gm0 < mv) {
                int row = g_rowsrc[gm0];
                float2 v;
                v.x = fmaxf(acc[mi][ni][0] + b0, 0.0f);
                v.y = fmaxf(acc[mi][ni][1] + b1, 0.0f);
                *(float2*)(g_H + (size_t)row * N_DIM + gn) = v;
            }
            int gm1 = gm0 + 8;
            if (gm1 < mv) {
                int row = g_rowsrc[gm1];
                float2 v;
                v.x = fmaxf(acc[mi][ni][2] + b0, 0.0f);
                v.y = fmaxf(acc[mi][ni][3] + b1, 0.0f);
                *(float2*)(g_H + (size_t)row * N_DIM + gn) = v;
            }
        }
    }
}

// ---------------- Kernel: per-frame head (valid boxes only, float4) ----------------
__global__ __launch_bounds__(256)
void head_kernel(const float* __restrict__ w_act,
                 const float* __restrict__ b_act,
                 const float* __restrict__ w_acty,
                 const float* __restrict__ b_acty,
                 const int*   __restrict__ bboxes_num,
                 float* __restrict__ out) {
    const int bt   = blockIdx.x;
    const int tid  = threadIdx.x;
    const int lane = tid & 31;
    const int warp = tid >> 5;

    int nvalid = bboxes_num[bt];
    nvalid = nvalid < 1 ? 1 : (nvalid > MAXN ? MAXN : nvalid);
    const float4* h4 = (const float4*)(g_H + (size_t)bt * MAXN * N_DIM);

    __shared__ float pooled[N_DIM];

    // masked max-pool over valid boxes: 256 threads x float4 = 1024 features
    {
        float4 m = h4[tid];
        for (int n = 1; n < nvalid; n++) {
            float4 v = h4[n * 256 + tid];
            m.x = fmaxf(m.x, v.x); m.y = fmaxf(m.y, v.y);
            m.z = fmaxf(m.z, v.z); m.w = fmaxf(m.w, v.w);
        }
        ((float4*)pooled)[tid] = m;
    }

    // actions: one warp per (n,a); only valid n computed, invalid -> 0
    const int total = nvalid * A_DIM;
    for (int p = warp; p < MAXN * A_DIM; p += 8) {
        int n = p / A_DIM;
        int a = p % A_DIM;
        if (p < total) {
            const float4* hr = h4 + n * 256;
            float s = 0.0f;
            for (int i = lane; i < 256; i += 32) {
                float4 hv = hr[i];
                int f = i * 4;
                s = fmaf(hv.x, w_act[(f + 0) * A_DIM + a], s);
                s = fmaf(hv.y, w_act[(f + 1) * A_DIM + a], s);
                s = fmaf(hv.z, w_act[(f + 2) * A_DIM + a], s);
                s = fmaf(hv.w, w_act[(f + 3) * A_DIM + a], s);
            }
            #pragma unroll
            for (int o = 16; o; o >>= 1) s += __shfl_xor_sync(0xFFFFFFFFu, s, o);
            if (lane == 0) out[(bt * MAXN + n) * A_DIM + a] = s + b_act[a];
        } else if (lane == 0) {
            out[(bt * MAXN + n) * A_DIM + a] = 0.0f;
        }
    }

    __syncthreads();

    // activities
    for (int g = warp; g < G_DIM; g += 8) {
        float s = 0.0f;
        for (int i = lane; i < 256; i += 32) {
            float4 pv = ((const float4*)pooled)[i];
            int f = i * 4;
            s = fmaf(pv.x, w_acty[(f + 0) * G_DIM + g], s);
            s = fmaf(pv.y, w_acty[(f + 1) * G_DIM + g], s);
            s = fmaf(pv.z, w_acty[(f + 2) * G_DIM + g], s);
            s = fmaf(pv.w, w_acty[(f + 3) * G_DIM + g], s);
        }
        #pragma unroll
        for (int o = 16; o; o >>= 1) s += __shfl_xor_sync(0xFFFFFFFFu, s, o);
        if (lane == 0)
            out[BT * MAXN * A_DIM + bt * G_DIM + g] = s + b_acty[g];
    }
}

// ---------------- launch ----------------
extern "C" void kernel_launch(void* const* d_in, const int* in_sizes, int n_in,
                              void* d_out, int out_size) {
    const float* X      = (const float*)d_in[0];
    const float* w_emb  = (const float*)d_in[1];
    const float* b_emb  = (const float*)d_in[2];
    const float* w_act  = (const float*)d_in[3];
    const float* b_act  = (const float*)d_in[4];
    const float* w_acty = (const float*)d_in[5];
    const float* b_acty = (const float*)d_in[6];
    const int*   bboxes = (const int*)d_in[7];
    float* out = (float*)d_out;

    cudaFuncSetAttribute(gemm_kernel, cudaFuncAttributeMaxDynamicSharedMemorySize, SMEM_TOTAL);

    prefix_kernel<<<1, 128>>>(bboxes);
    {
        size_t total = (size_t)M_DIM * (K_DIM / 4);
        int blocks = (int)((total + 255) / 256);
        convert_x_kernel<<<blocks, 256>>>(X);
    }
    {
        dim3 g(K_PAD / 64, N_DIM / 32);
        convert_w_kernel<<<g, 256>>>(w_emb);
    }
    {
        dim3 g(N_DIM / GN, (M_DIM + GM - 1) / GM);   // 16 x 17, ragged CTAs exit
        gemm_kernel<<<g, 256, SMEM_TOTAL>>>(b_emb);
    }
    head_kernel<<<BT, 256>>>(w_act, b_act, w_acty, b_acty, bboxes, out);
}